// round 1
// baseline (speedup 1.0000x reference)
#include <cuda_runtime.h>
#include <math.h>

// Problem constants
#define BB   512
#define TT   17
#define CC   1024
#define NH   16
#define HD   64
#define NL   12
#define MM   (BB*TT)          // 8704 tokens
#define KK7  7
#define HW28 28
#define PATCH_E 147           // 3*7*7
#define TOKB 8

// ---------------- scratch (device globals; no allocation) ----------------
__device__ float g_h [MM*CC];
__device__ float g_xn[MM*CC];
__device__ float g_q [MM*CC];
__device__ float g_k [MM*CC];
__device__ float g_v [MM*CC];
__device__ float g_w2[CC*PATCH_E];
__device__ float g_b2[PATCH_E];

// ---------------- embed: patchify + bilinear thumbnail token ----------------
// token 0: thumbnail (bilinear 28->7, half-pixel => avg of 4 pixels), tokens 1..16: 7x7 patches
__global__ void embed_kernel(const float* __restrict__ x, const float* __restrict__ cw)
{
    __shared__ float vec[TOKB][PATCH_E];
    const int tok0 = blockIdx.x * TOKB;
    const int tid  = threadIdx.x; // 256

    for (int idx = tid; idx < TOKB*PATCH_E; idx += 256) {
        int tt = idx / PATCH_E, e = idx % PATCH_E;
        int tok = tok0 + tt;
        int b = tok / TT, s = tok % TT;
        int c = e / 49, r = (e / 7) % 7, q = e % 7;
        const float* xb = x + ((size_t)(b*3 + c)) * (HW28*HW28);
        float val;
        if (s == 0) {
            int rr = 4*r + 1, qq = 4*q + 1;
            val = 0.25f * (xb[rr*HW28+qq]   + xb[rr*HW28+qq+1] +
                           xb[(rr+1)*HW28+qq] + xb[(rr+1)*HW28+qq+1]);
        } else {
            int p = s - 1; int i = p >> 2, j = p & 3;
            val = xb[(7*i + r)*HW28 + 7*j + q];
        }
        vec[tt][e] = val;
    }
    __syncthreads();

    for (int co = tid; co < CC; co += 256) {
        const float* w = cw + (size_t)co * PATCH_E;
        float acc[TOKB];
        #pragma unroll
        for (int t = 0; t < TOKB; t++) acc[t] = 0.f;
        for (int e = 0; e < PATCH_E; e++) {
            float wv = w[e];
            #pragma unroll
            for (int t = 0; t < TOKB; t++) acc[t] += vec[t][e] * wv;
        }
        #pragma unroll
        for (int t = 0; t < TOKB; t++)
            g_h[(size_t)(tok0+t)*CC + co] = acc[t];
    }
}

// ---------------- layernorm (token per block, 256 threads) ----------------
__global__ void ln_kernel(const float* __restrict__ src, float* __restrict__ dst,
                          const float* __restrict__ w, const float* __restrict__ b)
{
    const int tok = blockIdx.x;
    const int tid = threadIdx.x;
    float4 v = ((const float4*)(src + (size_t)tok*CC))[tid];
    float sum = v.x+v.y+v.z+v.w;
    float sq  = v.x*v.x+v.y*v.y+v.z*v.z+v.w*v.w;
    #pragma unroll
    for (int o = 16; o > 0; o >>= 1) {
        sum += __shfl_xor_sync(0xffffffffu, sum, o);
        sq  += __shfl_xor_sync(0xffffffffu, sq,  o);
    }
    __shared__ float ss[8], sqs[8];
    __shared__ float m_s, r_s;
    int wid = tid >> 5, lid = tid & 31;
    if (lid == 0) { ss[wid] = sum; sqs[wid] = sq; }
    __syncthreads();
    if (tid == 0) {
        float s = 0.f, q = 0.f;
        #pragma unroll
        for (int i = 0; i < 8; i++) { s += ss[i]; q += sqs[i]; }
        float m = s * (1.f/CC);
        float var = q * (1.f/CC) - m*m;
        m_s = m; r_s = rsqrtf(var + 1e-5f);
    }
    __syncthreads();
    float m = m_s, r = r_s;
    int c = tid * 4;
    float4 wv = *(const float4*)(w + c);
    float4 bv = *(const float4*)(b + c);
    float4 o;
    o.x = (v.x - m)*r*wv.x + bv.x;
    o.y = (v.y - m)*r*wv.y + bv.y;
    o.z = (v.z - m)*r*wv.z + bv.z;
    o.w = (v.w - m)*r*wv.w + bv.w;
    ((float4*)(dst + (size_t)tok*CC))[tid] = o;
}

// ---------------- GEMM: C[m,n] = sum_k A[m,k]*Bw[n,k] (+bias[n]) (+add[m,n]) ----------------
// M=8704 (68 tiles), N=1024 (8 tiles), K=1024.  128x128x8 tile, 256 thr, 8x8/thread.
__global__ __launch_bounds__(256, 2)
void gemm_tn(const float* __restrict__ A, const float* __restrict__ Bw,
             const float* __restrict__ bias, const float* __restrict__ add,
             float* __restrict__ C)
{
    __shared__ float As[8][128];
    __shared__ float Bs[8][128];
    const int bm = blockIdx.y * 128;
    const int bn = blockIdx.x * 128;
    const int tid  = threadIdx.x;
    const int tx   = tid & 15;
    const int ty   = tid >> 4;
    const int lrow = tid >> 1;
    const int lcol = (tid & 1) * 4;
    const float* Ap = A  + (size_t)(bm + lrow) * CC + lcol;
    const float* Bp = Bw + (size_t)(bn + lrow) * CC + lcol;

    float acc[8][8];
    #pragma unroll
    for (int i = 0; i < 8; i++)
        #pragma unroll
        for (int j = 0; j < 8; j++) acc[i][j] = 0.f;

    for (int k0 = 0; k0 < CC; k0 += 8) {
        float4 av = *(const float4*)(Ap + k0);
        float4 bv = *(const float4*)(Bp + k0);
        As[lcol+0][lrow] = av.x; As[lcol+1][lrow] = av.y;
        As[lcol+2][lrow] = av.z; As[lcol+3][lrow] = av.w;
        Bs[lcol+0][lrow] = bv.x; Bs[lcol+1][lrow] = bv.y;
        Bs[lcol+2][lrow] = bv.z; Bs[lcol+3][lrow] = bv.w;
        __syncthreads();
        #pragma unroll
        for (int kk = 0; kk < 8; kk++) {
            float4 a0 = *(const float4*)&As[kk][ty*8];
            float4 a1 = *(const float4*)&As[kk][ty*8+4];
            float4 b0 = *(const float4*)&Bs[kk][tx*8];
            float4 b1 = *(const float4*)&Bs[kk][tx*8+4];
            float af[8] = {a0.x,a0.y,a0.z,a0.w,a1.x,a1.y,a1.z,a1.w};
            float bf[8] = {b0.x,b0.y,b0.z,b0.w,b1.x,b1.y,b1.z,b1.w};
            #pragma unroll
            for (int i = 0; i < 8; i++)
                #pragma unroll
                for (int j = 0; j < 8; j++)
                    acc[i][j] += af[i]*bf[j];
        }
        __syncthreads();
    }

    #pragma unroll
    for (int i = 0; i < 8; i++) {
        int row = bm + ty*8 + i;
        float* cp = C + (size_t)row*CC + bn + tx*8;
        #pragma unroll
        for (int j4 = 0; j4 < 8; j4 += 4) {
            float4 o = make_float4(acc[i][j4], acc[i][j4+1], acc[i][j4+2], acc[i][j4+3]);
            if (bias) {
                const float4 bb = *(const float4*)(bias + bn + tx*8 + j4);
                o.x += bb.x; o.y += bb.y; o.z += bb.z; o.w += bb.w;
            }
            if (add) {
                const float4 rr = *(const float4*)(add + (size_t)row*CC + bn + tx*8 + j4);
                o.x += rr.x; o.y += rr.y; o.z += rr.z; o.w += rr.w;
            }
            *(float4*)(cp + j4) = o;
        }
    }
}

// ---------------- attention: causal softmax, T=17, hd=64; writes h += o ----------------
__global__ void attn_kernel()
{
    __shared__ float qs[TT][65], ks[TT][65], vs[TT][65], sc[TT][20];
    const int bh = blockIdx.x;
    const int b = bh >> 4, hh = bh & 15;
    const size_t base = (size_t)b*TT*CC + hh*HD;
    const int tid = threadIdx.x; // 128

    for (int idx = tid; idx < TT*HD; idx += 128) {
        int t = idx >> 6, d = idx & 63;
        size_t g = base + (size_t)t*CC + d;
        qs[t][d] = g_q[g]; ks[t][d] = g_k[g]; vs[t][d] = g_v[g];
    }
    __syncthreads();

    for (int e = tid; e < TT*TT; e += 128) {
        int qi = e / TT, kj = e % TT;
        if (kj <= qi) {
            float a = 0.f;
            #pragma unroll
            for (int d = 0; d < HD; d++) a += qs[qi][d]*ks[kj][d];
            sc[qi][kj] = a * 0.125f;   // 1/sqrt(64)
        }
    }
    __syncthreads();

    if (tid < TT) {
        int t = tid;
        float m = -1e30f;
        for (int j = 0; j <= t; j++) m = fmaxf(m, sc[t][j]);
        float s = 0.f;
        for (int j = 0; j <= t; j++) { float e2 = __expf(sc[t][j]-m); sc[t][j] = e2; s += e2; }
        float inv = 1.f/s;
        for (int j = 0; j <= t; j++) sc[t][j] *= inv;
    }
    __syncthreads();

    for (int e = tid; e < TT*HD; e += 128) {
        int t = e >> 6, d = e & 63;
        float a = 0.f;
        for (int j = 0; j <= t; j++) a += sc[t][j]*vs[j][d];
        g_h[base + (size_t)t*CC + d] += a;
    }
}

// ---------------- fold out_w into conv decode: W2[e,n] = sum_c out_w[c,e]*cw[c,n] ----------------
__global__ void w2_kernel(const float* __restrict__ out_w, const float* __restrict__ cw)
{
    __shared__ float col[CC];
    const int e = blockIdx.x;
    const int tid = threadIdx.x; // 256
    for (int c = tid; c < CC; c += 256) col[c] = out_w[(size_t)c*CC + e];
    __syncthreads();
    if (tid < PATCH_E) {
        float acc = 0.f;
        for (int c = 0; c < CC; c++) acc += col[c]*cw[(size_t)c*PATCH_E + tid];
        g_w2[(size_t)e*PATCH_E + tid] = acc;
    }
}

__global__ void b2_kernel(const float* __restrict__ out_b, const float* __restrict__ cw)
{
    const int n = threadIdx.x;
    if (n < PATCH_E) {
        float acc = 0.f;
        for (int c = 0; c < CC; c++) acc += out_b[c]*cw[(size_t)c*PATCH_E + n];
        g_b2[n] = acc;
    }
}

// ---------------- decode: out[b,d,hr,s*7+w] = sum_e h[b,s,e]*W2[e,n] + b2[n] ----------------
__global__ void decode_kernel(float* __restrict__ out)
{
    __shared__ float sh[TOKB][CC];
    const int tok0 = blockIdx.x * TOKB;
    const int tid = threadIdx.x; // 256
    const float4* src = (const float4*)(g_h + (size_t)tok0*CC);
    for (int idx = tid; idx < TOKB*CC/4; idx += 256)
        ((float4*)sh)[idx] = src[idx];
    __syncthreads();

    const int n = tid;
    if (n < PATCH_E) {
        float acc[TOKB];
        #pragma unroll
        for (int t = 0; t < TOKB; t++) acc[t] = 0.f;
        for (int e = 0; e < CC; e++) {
            float wv = g_w2[(size_t)e*PATCH_E + n];
            #pragma unroll
            for (int t = 0; t < TOKB; t++) acc[t] += sh[t][e]*wv;
        }
        float bb = g_b2[n];
        int d = n / 49, hr = (n % 49) / 7, w = n % 7;
        #pragma unroll
        for (int t = 0; t < TOKB; t++) {
            int tok = tok0 + t;
            int b = tok / TT, s = tok % TT;
            out[((size_t)(b*3 + d)*7 + hr)*119 + s*7 + w] = acc[t] + bb;
        }
    }
}

// ---------------- launch ----------------
extern "C" void kernel_launch(void* const* d_in, const int* in_sizes, int n_in,
                              void* d_out, int out_size)
{
    const float* x      = (const float*)d_in[0];
    const float* conv_w = (const float*)d_in[1];
    const float* ln1_w  = (const float*)d_in[2];
    const float* ln1_b  = (const float*)d_in[3];
    const float* wq     = (const float*)d_in[4];
    const float* wk     = (const float*)d_in[5];
    const float* wv     = (const float*)d_in[6];
    const float* ln2_w  = (const float*)d_in[7];
    const float* ln2_b  = (const float*)d_in[8];
    const float* mlp_w  = (const float*)d_in[9];
    const float* mlp_b  = (const float*)d_in[10];
    const float* out_w  = (const float*)d_in[11];
    const float* out_b  = (const float*)d_in[12];
    float* out = (float*)d_out;

    void *ph, *pxn, *pq, *pk, *pv;
    cudaGetSymbolAddress(&ph,  g_h);
    cudaGetSymbolAddress(&pxn, g_xn);
    cudaGetSymbolAddress(&pq,  g_q);
    cudaGetSymbolAddress(&pk,  g_k);
    cudaGetSymbolAddress(&pv,  g_v);
    float* h  = (float*)ph;
    float* xn = (float*)pxn;
    float* q  = (float*)pq;
    float* k  = (float*)pk;
    float* v  = (float*)pv;

    embed_kernel<<<MM/TOKB, 256>>>(x, conv_w);

    dim3 ggrid(CC/128, MM/128); // (8, 68)
    for (int l = 0; l < NL; l++) {
        const size_t wo = (size_t)l*CC*CC;
        const size_t vo = (size_t)l*CC;
        ln_kernel<<<MM, 256>>>(h, xn, ln1_w + vo, ln1_b + vo);
        gemm_tn<<<ggrid, 256>>>(xn, wq + wo, nullptr, nullptr, q);
        gemm_tn<<<ggrid, 256>>>(xn, wk + wo, nullptr, nullptr, k);
        gemm_tn<<<ggrid, 256>>>(xn, wv + wo, nullptr, nullptr, v);
        attn_kernel<<<BB*NH, 128>>>();
        ln_kernel<<<MM, 256>>>(h, xn, ln2_w + vo, ln2_b + vo);
        gemm_tn<<<ggrid, 256>>>(xn, mlp_w + wo, mlp_b + vo, h, h);
    }

    w2_kernel<<<CC, 256>>>(out_w, conv_w);
    b2_kernel<<<1, 160>>>(out_b, conv_w);
    decode_kernel<<<MM/TOKB, 256>>>(out);
}

// round 3
// speedup vs baseline: 2.9217x; 2.9217x over previous
#include <cuda_runtime.h>
#include <math.h>
#include <stdint.h>

// Problem constants
#define BB   512
#define TT   17
#define CC   1024
#define NH   16
#define HD   64
#define NL   12
#define MM   (BB*TT)          // 8704 tokens
#define HW28 28
#define PATCH_E 147           // 3*7*7
#define TOKB 8

// ---------------- scratch (device globals; no allocation) ----------------
__device__ float g_h [MM*CC];
__device__ float g_xn[MM*CC];
__device__ float g_q [MM*CC];
__device__ float g_k [MM*CC];
__device__ float g_v [MM*CC];
__device__ float g_w2[CC*PATCH_E];
__device__ float g_b2[PATCH_E];

// ---------------- helpers ----------------
__device__ __forceinline__ uint32_t f2tf(float f) {
    uint32_t u;
    asm("cvt.rna.tf32.f32 %0, %1;" : "=r"(u) : "f"(f));
    return u;
}

__device__ __forceinline__ void mma_tf32(float* c, const uint32_t* a, const uint32_t* b) {
    asm volatile(
        "mma.sync.aligned.m16n8k8.row.col.f32.tf32.tf32.f32 "
        "{%0,%1,%2,%3}, {%4,%5,%6,%7}, {%8,%9}, {%0,%1,%2,%3};"
        : "+f"(c[0]), "+f"(c[1]), "+f"(c[2]), "+f"(c[3])
        : "r"(a[0]), "r"(a[1]), "r"(a[2]), "r"(a[3]), "r"(b[0]), "r"(b[1]));
}

// ---------------- embed: patchify + bilinear thumbnail token ----------------
__global__ void embed_kernel(const float* __restrict__ x, const float* __restrict__ cw)
{
    __shared__ float vec[TOKB][PATCH_E];
    const int tok0 = blockIdx.x * TOKB;
    const int tid  = threadIdx.x; // 256

    for (int idx = tid; idx < TOKB*PATCH_E; idx += 256) {
        int tt = idx / PATCH_E, e = idx % PATCH_E;
        int tok = tok0 + tt;
        int b = tok / TT, s = tok % TT;
        int c = e / 49, r = (e / 7) % 7, q = e % 7;
        const float* xb = x + ((size_t)(b*3 + c)) * (HW28*HW28);
        float val;
        if (s == 0) {
            int rr = 4*r + 1, qq = 4*q + 1;
            val = 0.25f * (xb[rr*HW28+qq]   + xb[rr*HW28+qq+1] +
                           xb[(rr+1)*HW28+qq] + xb[(rr+1)*HW28+qq+1]);
        } else {
            int p = s - 1; int i = p >> 2, j = p & 3;
            val = xb[(7*i + r)*HW28 + 7*j + q];
        }
        vec[tt][e] = val;
    }
    __syncthreads();

    for (int co = tid; co < CC; co += 256) {
        const float* w = cw + (size_t)co * PATCH_E;
        float acc[TOKB];
        #pragma unroll
        for (int t = 0; t < TOKB; t++) acc[t] = 0.f;
        for (int e = 0; e < PATCH_E; e++) {
            float wv = w[e];
            #pragma unroll
            for (int t = 0; t < TOKB; t++) acc[t] += vec[t][e] * wv;
        }
        #pragma unroll
        for (int t = 0; t < TOKB; t++)
            g_h[(size_t)(tok0+t)*CC + co] = acc[t];
    }
}

// ---------------- layernorm ----------------
__global__ void ln_kernel(const float* __restrict__ src, float* __restrict__ dst,
                          const float* __restrict__ w, const float* __restrict__ b)
{
    const int tok = blockIdx.x;
    const int tid = threadIdx.x;
    float4 v = ((const float4*)(src + (size_t)tok*CC))[tid];
    float sum = v.x+v.y+v.z+v.w;
    float sq  = v.x*v.x+v.y*v.y+v.z*v.z+v.w*v.w;
    #pragma unroll
    for (int o = 16; o > 0; o >>= 1) {
        sum += __shfl_xor_sync(0xffffffffu, sum, o);
        sq  += __shfl_xor_sync(0xffffffffu, sq,  o);
    }
    __shared__ float ss[8], sqs[8];
    __shared__ float m_s, r_s;
    int wid = tid >> 5, lid = tid & 31;
    if (lid == 0) { ss[wid] = sum; sqs[wid] = sq; }
    __syncthreads();
    if (tid == 0) {
        float s = 0.f, q = 0.f;
        #pragma unroll
        for (int i = 0; i < 8; i++) { s += ss[i]; q += sqs[i]; }
        float m = s * (1.f/CC);
        float var = q * (1.f/CC) - m*m;
        m_s = m; r_s = rsqrtf(var + 1e-5f);
    }
    __syncthreads();
    float m = m_s, r = r_s;
    int c = tid * 4;
    float4 wv = *(const float4*)(w + c);
    float4 bv = *(const float4*)(b + c);
    float4 o;
    o.x = (v.x - m)*r*wv.x + bv.x;
    o.y = (v.y - m)*r*wv.y + bv.y;
    o.z = (v.z - m)*r*wv.z + bv.z;
    o.w = (v.w - m)*r*wv.w + bv.w;
    ((float4*)(dst + (size_t)tok*CC))[tid] = o;
}

// ---------------- tf32 tensor-core GEMM ----------------
// C[m,n] = sum_k A[m,k]*Bw[n,k] (+bias[n]) (+add[m,n])
// Tile 128x128, KC=16, 8 warps, warp tile 64x32 (4x4 m16n8k8 atoms), double buffered.
#define KC 16
#define SSTR 20   // smem row stride in floats (conflict-free fragment reads)

__global__ __launch_bounds__(256, 2)
void gemm_tc(const float* __restrict__ A, const float* __restrict__ Bw,
             const float* __restrict__ bias, const float* __restrict__ add,
             float* __restrict__ C)
{
    __shared__ uint32_t As[2][128][SSTR];
    __shared__ uint32_t Bs[2][128][SSTR];

    const int bm = blockIdx.y * 128;
    const int bn = blockIdx.x * 128;
    const int tid  = threadIdx.x;
    const int wid  = tid >> 5;
    const int lane = tid & 31;
    const int wm = (wid & 1) * 64;    // warp m offset
    const int wn = (wid >> 1) * 32;   // warp n offset
    const int g  = lane >> 2;         // group id 0..7
    const int tg = lane & 3;          // thread in group 0..3

    // gmem load mapping: 256 thr, each loads 2 float4 per matrix per chunk
    const int lrow = tid >> 2;        // 0..63
    const int lc4  = (tid & 3) * 4;   // float col 0,4,8,12
    const float* Ap = A  + (size_t)(bm + lrow) * CC + lc4;
    const float* Bp = Bw + (size_t)(bn + lrow) * CC + lc4;

    float acc[4][4][4];
    #pragma unroll
    for (int i = 0; i < 4; i++)
        #pragma unroll
        for (int j = 0; j < 4; j++)
            #pragma unroll
            for (int t = 0; t < 4; t++) acc[i][j][t] = 0.f;

    float4 pa0, pa1, pb0, pb1;
    pa0 = *(const float4*)(Ap);
    pa1 = *(const float4*)(Ap + (size_t)64*CC);
    pb0 = *(const float4*)(Bp);
    pb1 = *(const float4*)(Bp + (size_t)64*CC);

    // store prefetch regs into smem buffer
    auto sts = [&](int buf) {
        uint32_t* d0 = &As[buf][lrow][lc4];
        d0[0]=f2tf(pa0.x); d0[1]=f2tf(pa0.y); d0[2]=f2tf(pa0.z); d0[3]=f2tf(pa0.w);
        uint32_t* d1 = &As[buf][lrow+64][lc4];
        d1[0]=f2tf(pa1.x); d1[1]=f2tf(pa1.y); d1[2]=f2tf(pa1.z); d1[3]=f2tf(pa1.w);
        uint32_t* e0 = &Bs[buf][lrow][lc4];
        e0[0]=f2tf(pb0.x); e0[1]=f2tf(pb0.y); e0[2]=f2tf(pb0.z); e0[3]=f2tf(pb0.w);
        uint32_t* e1 = &Bs[buf][lrow+64][lc4];
        e1[0]=f2tf(pb1.x); e1[1]=f2tf(pb1.y); e1[2]=f2tf(pb1.z); e1[3]=f2tf(pb1.w);
    };

    sts(0);
    __syncthreads();

    const int NCH = CC / KC; // 64 chunks
    for (int c = 0; c < NCH; c++) {
        const int cur = c & 1;
        if (c + 1 < NCH) {
            const size_t k0 = (size_t)(c + 1) * KC;
            pa0 = *(const float4*)(Ap + k0);
            pa1 = *(const float4*)(Ap + (size_t)64*CC + k0);
            pb0 = *(const float4*)(Bp + k0);
            pb1 = *(const float4*)(Bp + (size_t)64*CC + k0);
        }

        #pragma unroll
        for (int ka = 0; ka < 2; ka++) {
            const int kc = ka * 8 + tg;
            uint32_t afr[4][4], bfr[4][2];
            #pragma unroll
            for (int ma = 0; ma < 4; ma++) {
                const int r0 = wm + ma*16 + g;
                afr[ma][0] = As[cur][r0   ][kc];
                afr[ma][1] = As[cur][r0+8 ][kc];
                afr[ma][2] = As[cur][r0   ][kc+4];
                afr[ma][3] = As[cur][r0+8 ][kc+4];
            }
            #pragma unroll
            for (int na = 0; na < 4; na++) {
                const int n0 = wn + na*8 + g;
                bfr[na][0] = Bs[cur][n0][kc];
                bfr[na][1] = Bs[cur][n0][kc+4];
            }
            #pragma unroll
            for (int ma = 0; ma < 4; ma++)
                #pragma unroll
                for (int na = 0; na < 4; na++)
                    mma_tf32(acc[ma][na], afr[ma], bfr[na]);
        }

        if (c + 1 < NCH) {
            // Writes go to buffer (1-cur); its last readers finished before the
            // barrier at the end of iteration c-1, so a single barrier suffices.
            sts(1 - cur);
            __syncthreads();
        }
    }

    // epilogue: c0/c1 at (row, tg*2 / +1); c2/c3 at (row+8, ...)
    #pragma unroll
    for (int ma = 0; ma < 4; ma++) {
        #pragma unroll
        for (int half = 0; half < 2; half++) {
            const int row = bm + wm + ma*16 + g + half*8;
            float* cp = C + (size_t)row * CC + bn + wn;
            #pragma unroll
            for (int na = 0; na < 4; na++) {
                const int col = na*8 + tg*2;
                float2 o;
                o.x = acc[ma][na][half*2 + 0];
                o.y = acc[ma][na][half*2 + 1];
                if (bias) {
                    const float2 bb = *(const float2*)(bias + bn + wn + col);
                    o.x += bb.x; o.y += bb.y;
                }
                if (add) {
                    const float2 rr = *(const float2*)(add + (size_t)row*CC + bn + wn + col);
                    o.x += rr.x; o.y += rr.y;
                }
                *(float2*)(cp + col) = o;
            }
        }
    }
}

// ---------------- attention: causal softmax, T=17, hd=64; writes h += o ----------------
__global__ void attn_kernel()
{
    __shared__ float qs[TT][65], ks[TT][65], vs[TT][65], sc[TT][20];
    const int bh = blockIdx.x;
    const int b = bh >> 4, hh = bh & 15;
    const size_t base = (size_t)b*TT*CC + hh*HD;
    const int tid = threadIdx.x; // 128

    for (int idx = tid; idx < TT*HD; idx += 128) {
        int t = idx >> 6, d = idx & 63;
        size_t gg = base + (size_t)t*CC + d;
        qs[t][d] = g_q[gg]; ks[t][d] = g_k[gg]; vs[t][d] = g_v[gg];
    }
    __syncthreads();

    for (int e = tid; e < TT*TT; e += 128) {
        int qi = e / TT, kj = e % TT;
        if (kj <= qi) {
            float a = 0.f;
            #pragma unroll
            for (int d = 0; d < HD; d++) a += qs[qi][d]*ks[kj][d];
            sc[qi][kj] = a * 0.125f;
        }
    }
    __syncthreads();

    if (tid < TT) {
        int t = tid;
        float m = -1e30f;
        for (int j = 0; j <= t; j++) m = fmaxf(m, sc[t][j]);
        float s = 0.f;
        for (int j = 0; j <= t; j++) { float e2 = __expf(sc[t][j]-m); sc[t][j] = e2; s += e2; }
        float inv = 1.f/s;
        for (int j = 0; j <= t; j++) sc[t][j] *= inv;
    }
    __syncthreads();

    for (int e = tid; e < TT*HD; e += 128) {
        int t = e >> 6, d = e & 63;
        float a = 0.f;
        for (int j = 0; j <= t; j++) a += sc[t][j]*vs[j][d];
        g_h[base + (size_t)t*CC + d] += a;
    }
}

// ---------------- fold out_w into conv decode ----------------
__global__ void w2_kernel(const float* __restrict__ out_w, const float* __restrict__ cw)
{
    __shared__ float col[CC];
    const int e = blockIdx.x;
    const int tid = threadIdx.x; // 256
    for (int c = tid; c < CC; c += 256) col[c] = out_w[(size_t)c*CC + e];
    __syncthreads();
    if (tid < PATCH_E) {
        float acc = 0.f;
        for (int c = 0; c < CC; c++) acc += col[c]*cw[(size_t)c*PATCH_E + tid];
        g_w2[(size_t)e*PATCH_E + tid] = acc;
    }
}

__global__ void b2_kernel(const float* __restrict__ out_b, const float* __restrict__ cw)
{
    const int n = threadIdx.x;
    if (n < PATCH_E) {
        float acc = 0.f;
        for (int c = 0; c < CC; c++) acc += out_b[c]*cw[(size_t)c*PATCH_E + n];
        g_b2[n] = acc;
    }
}

// ---------------- decode ----------------
__global__ void decode_kernel(float* __restrict__ out)
{
    __shared__ float sh[TOKB][CC];
    const int tok0 = blockIdx.x * TOKB;
    const int tid = threadIdx.x; // 256
    const float4* src = (const float4*)(g_h + (size_t)tok0*CC);
    for (int idx = tid; idx < TOKB*CC/4; idx += 256)
        ((float4*)sh)[idx] = src[idx];
    __syncthreads();

    const int n = tid;
    if (n < PATCH_E) {
        float acc[TOKB];
        #pragma unroll
        for (int t = 0; t < TOKB; t++) acc[t] = 0.f;
        for (int e = 0; e < CC; e++) {
            float wv = g_w2[(size_t)e*PATCH_E + n];
            #pragma unroll
            for (int t = 0; t < TOKB; t++) acc[t] += sh[t][e]*wv;
        }
        float bb = g_b2[n];
        int d = n / 49, hr = (n % 49) / 7, w = n % 7;
        #pragma unroll
        for (int t = 0; t < TOKB; t++) {
            int tok = tok0 + t;
            int b = tok / TT, s = tok % TT;
            out[((size_t)(b*3 + d)*7 + hr)*119 + s*7 + w] = acc[t] + bb;
        }
    }
}

// ---------------- launch ----------------
extern "C" void kernel_launch(void* const* d_in, const int* in_sizes, int n_in,
                              void* d_out, int out_size)
{
    const float* x      = (const float*)d_in[0];
    const float* conv_w = (const float*)d_in[1];
    const float* ln1_w  = (const float*)d_in[2];
    const float* ln1_b  = (const float*)d_in[3];
    const float* wq     = (const float*)d_in[4];
    const float* wk     = (const float*)d_in[5];
    const float* wv     = (const float*)d_in[6];
    const float* ln2_w  = (const float*)d_in[7];
    const float* ln2_b  = (const float*)d_in[8];
    const float* mlp_w  = (const float*)d_in[9];
    const float* mlp_b  = (const float*)d_in[10];
    const float* out_w  = (const float*)d_in[11];
    const float* out_b  = (const float*)d_in[12];
    float* out = (float*)d_out;

    void *ph, *pxn, *pq, *pk, *pv;
    cudaGetSymbolAddress(&ph,  g_h);
    cudaGetSymbolAddress(&pxn, g_xn);
    cudaGetSymbolAddress(&pq,  g_q);
    cudaGetSymbolAddress(&pk,  g_k);
    cudaGetSymbolAddress(&pv,  g_v);
    float* h  = (float*)ph;
    float* xn = (float*)pxn;
    float* q  = (float*)pq;
    float* k  = (float*)pk;
    float* v  = (float*)pv;

    embed_kernel<<<MM/TOKB, 256>>>(x, conv_w);

    dim3 ggrid(CC/128, MM/128); // (8, 68)
    for (int l = 0; l < NL; l++) {
        const size_t wo = (size_t)l*CC*CC;
        const size_t vo = (size_t)l*CC;
        ln_kernel<<<MM, 256>>>(h, xn, ln1_w + vo, ln1_b + vo);
        gemm_tc<<<ggrid, 256>>>(xn, wq + wo, nullptr, nullptr, q);
        gemm_tc<<<ggrid, 256>>>(xn, wk + wo, nullptr, nullptr, k);
        gemm_tc<<<ggrid, 256>>>(xn, wv + wo, nullptr, nullptr, v);
        attn_kernel<<<BB*NH, 128>>>();
        ln_kernel<<<MM, 256>>>(h, xn, ln2_w + vo, ln2_b + vo);
        gemm_tc<<<ggrid, 256>>>(xn, mlp_w + wo, mlp_b + vo, h, h);
    }

    w2_kernel<<<CC, 256>>>(out_w, conv_w);
    b2_kernel<<<1, 160>>>(out_b, conv_w);
    decode_kernel<<<MM/TOKB, 256>>>(out);
}

// round 4
// speedup vs baseline: 5.5705x; 1.9066x over previous
#include <cuda_runtime.h>
#include <cuda_fp16.h>
#include <math.h>
#include <stdint.h>

// Problem constants
#define BB   512
#define TT   17
#define CC   1024
#define NH   16
#define HD   64
#define NL   12
#define MM   (BB*TT)          // 8704 tokens
#define HW28 28
#define PATCH_E 147           // 3*7*7
#define TOKB 8
#define BK   32               // gemm k-chunk (fp16)

// ---------------- scratch (device globals; no allocation) ----------------
__device__ float  g_h   [MM*CC];
__device__ __half g_xn16[MM*CC];
__device__ float  g_qkv [(size_t)MM*3*CC];
__device__ __half g_wqkv16[(size_t)NL*3*CC*CC];
__device__ __half g_wmlp16[(size_t)NL*CC*CC];
__device__ float  g_w2[CC*PATCH_E];
__device__ float  g_b2[PATCH_E];

// ---------------- mma / ldmatrix helpers ----------------
__device__ __forceinline__ void mma_fp16(float* c, const uint32_t* a, const uint32_t* b) {
    asm volatile(
        "mma.sync.aligned.m16n8k16.row.col.f32.f16.f16.f32 "
        "{%0,%1,%2,%3}, {%4,%5,%6,%7}, {%8,%9}, {%0,%1,%2,%3};"
        : "+f"(c[0]), "+f"(c[1]), "+f"(c[2]), "+f"(c[3])
        : "r"(a[0]), "r"(a[1]), "r"(a[2]), "r"(a[3]), "r"(b[0]), "r"(b[1]));
}

__device__ __forceinline__ void ldm4(uint32_t* r, uint32_t addr) {
    asm volatile("ldmatrix.sync.aligned.m8n8.x4.shared.b16 {%0,%1,%2,%3}, [%4];"
        : "=r"(r[0]), "=r"(r[1]), "=r"(r[2]), "=r"(r[3]) : "r"(addr));
}

// ---------------- weight pack: fp32 -> fp16 ----------------
__global__ void pack_qkv_kernel(const float* __restrict__ wq, const float* __restrict__ wk,
                                const float* __restrict__ wv)
{
    const size_t per = (size_t)CC*CC/4;     // float4 per matrix
    size_t i = (size_t)blockIdx.x*blockDim.x + threadIdx.x;
    if (i >= (size_t)NL*3*per) return;
    size_t l = i / (3*per), rem = i % (3*per);
    int sel = (int)(rem / per); size_t j = rem % per;
    const float* src = (sel==0 ? wq : (sel==1 ? wk : wv)) + l*CC*CC;
    float4 v = ((const float4*)src)[j];
    __half2 h0 = __floats2half2_rn(v.x, v.y);
    __half2 h1 = __floats2half2_rn(v.z, v.w);
    __half2* dst = (__half2*)(g_wqkv16 + i*4);
    dst[0] = h0; dst[1] = h1;
}

__global__ void pack_mlp_kernel(const float* __restrict__ wm)
{
    size_t i = (size_t)blockIdx.x*blockDim.x + threadIdx.x;
    if (i >= (size_t)NL*CC*CC/4) return;
    float4 v = ((const float4*)wm)[i];
    __half2 h0 = __floats2half2_rn(v.x, v.y);
    __half2 h1 = __floats2half2_rn(v.z, v.w);
    __half2* dst = (__half2*)(g_wmlp16 + i*4);
    dst[0] = h0; dst[1] = h1;
}

// ---------------- embed: patchify + bilinear thumbnail token ----------------
__global__ void embed_kernel(const float* __restrict__ x, const float* __restrict__ cw)
{
    __shared__ float vec[TOKB][PATCH_E];
    const int tok0 = blockIdx.x * TOKB;
    const int tid  = threadIdx.x; // 256

    for (int idx = tid; idx < TOKB*PATCH_E; idx += 256) {
        int tt = idx / PATCH_E, e = idx % PATCH_E;
        int tok = tok0 + tt;
        int b = tok / TT, s = tok % TT;
        int c = e / 49, r = (e / 7) % 7, q = e % 7;
        const float* xb = x + ((size_t)(b*3 + c)) * (HW28*HW28);
        float val;
        if (s == 0) {
            int rr = 4*r + 1, qq = 4*q + 1;
            val = 0.25f * (xb[rr*HW28+qq]   + xb[rr*HW28+qq+1] +
                           xb[(rr+1)*HW28+qq] + xb[(rr+1)*HW28+qq+1]);
        } else {
            int p = s - 1; int i = p >> 2, j = p & 3;
            val = xb[(7*i + r)*HW28 + 7*j + q];
        }
        vec[tt][e] = val;
    }
    __syncthreads();

    for (int co = tid; co < CC; co += 256) {
        const float* w = cw + (size_t)co * PATCH_E;
        float acc[TOKB];
        #pragma unroll
        for (int t = 0; t < TOKB; t++) acc[t] = 0.f;
        for (int e = 0; e < PATCH_E; e++) {
            float wv = w[e];
            #pragma unroll
            for (int t = 0; t < TOKB; t++) acc[t] += vec[t][e] * wv;
        }
        #pragma unroll
        for (int t = 0; t < TOKB; t++)
            g_h[(size_t)(tok0+t)*CC + co] = acc[t];
    }
}

// ---------------- layernorm: fp32 in, fp16 out ----------------
__global__ void ln_kernel(const float* __restrict__ src, __half* __restrict__ dst,
                          const float* __restrict__ w, const float* __restrict__ b)
{
    const int tok = blockIdx.x;
    const int tid = threadIdx.x;
    float4 v = ((const float4*)(src + (size_t)tok*CC))[tid];
    float sum = v.x+v.y+v.z+v.w;
    float sq  = v.x*v.x+v.y*v.y+v.z*v.z+v.w*v.w;
    #pragma unroll
    for (int o = 16; o > 0; o >>= 1) {
        sum += __shfl_xor_sync(0xffffffffu, sum, o);
        sq  += __shfl_xor_sync(0xffffffffu, sq,  o);
    }
    __shared__ float ss[8], sqs[8];
    __shared__ float m_s, r_s;
    int wid = tid >> 5, lid = tid & 31;
    if (lid == 0) { ss[wid] = sum; sqs[wid] = sq; }
    __syncthreads();
    if (tid == 0) {
        float s = 0.f, q = 0.f;
        #pragma unroll
        for (int i = 0; i < 8; i++) { s += ss[i]; q += sqs[i]; }
        float m = s * (1.f/CC);
        float var = q * (1.f/CC) - m*m;
        m_s = m; r_s = rsqrtf(var + 1e-5f);
    }
    __syncthreads();
    float m = m_s, r = r_s;
    int c = tid * 4;
    float4 wv = *(const float4*)(w + c);
    float4 bv = *(const float4*)(b + c);
    __half2 o0 = __floats2half2_rn((v.x - m)*r*wv.x + bv.x, (v.y - m)*r*wv.y + bv.y);
    __half2 o1 = __floats2half2_rn((v.z - m)*r*wv.z + bv.z, (v.w - m)*r*wv.w + bv.w);
    __half2* dp = (__half2*)(dst + (size_t)tok*CC + c);
    dp[0] = o0; dp[1] = o1;
}

// ---------------- fp16 tensor-core GEMM ----------------
// C[m,n] = sum_k A[m,k]*Bw[n,k] (+bias[n]) (+add[m,n]); A,Bw fp16 K-major (stride CC), C fp32 stride N.
// 128x128 tile, BK=32, 8 warps (64x32 each), cp.async double buffer, ldmatrix fragments.
__global__ __launch_bounds__(256, 2)
void gemm_fp16(const __half* __restrict__ A, const __half* __restrict__ Bw, int N,
               const float* __restrict__ bias, const float* __restrict__ add,
               float* __restrict__ C)
{
    __shared__ __half As[2][128*BK];
    __shared__ __half Bs[2][128*BK];

    const int bm = blockIdx.y * 128;
    const int bn = blockIdx.x * 128;
    const int tid  = threadIdx.x;
    const int wid  = tid >> 5;
    const int lane = tid & 31;
    const int wm = (wid & 1) * 64;
    const int wn = (wid >> 1) * 32;
    const int g  = lane >> 2;
    const int tg = lane & 3;

    // cp.async mapping: thread -> row lr (0..127), chunk pair lcp (0 or 2); 2x16B per matrix
    const int lr  = tid >> 1;
    const int lcp = (tid & 1) * 2;
    const int sw  = (lr >> 1) & 3;
    const __half* Ag = A  + (size_t)(bm + lr)*CC + lcp*8;
    const __half* Bg = Bw + (size_t)(bn + lr)*CC + lcp*8;

    uint32_t As_addr[2], Bs_addr[2];
    As_addr[0] = (uint32_t)__cvta_generic_to_shared(&As[0][0]);
    As_addr[1] = (uint32_t)__cvta_generic_to_shared(&As[1][0]);
    Bs_addr[0] = (uint32_t)__cvta_generic_to_shared(&Bs[0][0]);
    Bs_addr[1] = (uint32_t)__cvta_generic_to_shared(&Bs[1][0]);

    auto issue = [&](int buf, int k0) {
        #pragma unroll
        for (int i = 0; i < 2; i++) {
            int phys = (lcp + i) ^ sw;
            uint32_t da = As_addr[buf] + (lr*BK + phys*8)*2;
            uint32_t db = Bs_addr[buf] + (lr*BK + phys*8)*2;
            const void* sa = (const void*)(Ag + k0 + i*8);
            const void* sb = (const void*)(Bg + k0 + i*8);
            asm volatile("cp.async.cg.shared.global [%0], [%1], 16;" :: "r"(da), "l"(sa));
            asm volatile("cp.async.cg.shared.global [%0], [%1], 16;" :: "r"(db), "l"(sb));
        }
        asm volatile("cp.async.commit_group;");
    };

    // ldmatrix lane address components
    const int rowA = wm + (lane & 15);
    const int aHi  = lane >> 4;
    const int swA  = (rowA >> 1) & 3;
    const int rowB = wn + (lane & 7) + ((lane >> 4) << 3);
    const int bHi  = (lane >> 3) & 1;
    const int swB  = (rowB >> 1) & 3;

    float acc[4][4][4];
    #pragma unroll
    for (int i = 0; i < 4; i++)
        #pragma unroll
        for (int j = 0; j < 4; j++)
            #pragma unroll
            for (int t = 0; t < 4; t++) acc[i][j][t] = 0.f;

    issue(0, 0);

    const int NCH = CC / BK; // 32
    for (int cc = 0; cc < NCH; cc++) {
        asm volatile("cp.async.wait_group 0;");
        __syncthreads();
        const int cur = cc & 1;
        if (cc + 1 < NCH) issue(1 - cur, (cc + 1) * BK);

        const uint32_t abase = As_addr[cur] + rowA * (BK*2);
        const uint32_t bbase = Bs_addr[cur] + rowB * (BK*2);

        #pragma unroll
        for (int ks = 0; ks < 2; ks++) {
            const uint32_t pa = (uint32_t)(((ks*2 + aHi) ^ swA) * 16);
            const uint32_t pb = (uint32_t)(((ks*2 + bHi) ^ swB) * 16);
            uint32_t af[4][4], bf[2][4];
            #pragma unroll
            for (int ma = 0; ma < 4; ma++)
                ldm4(af[ma], abase + ma*(16*BK*2) + pa);
            #pragma unroll
            for (int np = 0; np < 2; np++)
                ldm4(bf[np], bbase + np*(16*BK*2) + pb);
            #pragma unroll
            for (int ma = 0; ma < 4; ma++)
                #pragma unroll
                for (int na = 0; na < 4; na++)
                    mma_fp16(acc[ma][na], af[ma], &bf[na>>1][(na&1)*2]);
        }
    }

    // epilogue: c0/c1 at (row=g+half*8, col=2tg); c2/c3 row+8
    #pragma unroll
    for (int ma = 0; ma < 4; ma++) {
        #pragma unroll
        for (int half = 0; half < 2; half++) {
            const int row = bm + wm + ma*16 + g + half*8;
            float* cp = C + (size_t)row * N + bn + wn;
            #pragma unroll
            for (int na = 0; na < 4; na++) {
                const int col = na*8 + tg*2;
                float2 o;
                o.x = acc[ma][na][half*2 + 0];
                o.y = acc[ma][na][half*2 + 1];
                if (bias) {
                    const float2 bb = *(const float2*)(bias + bn + wn + col);
                    o.x += bb.x; o.y += bb.y;
                }
                if (add) {
                    const float2 rr = *(const float2*)(add + (size_t)row*N + bn + wn + col);
                    o.x += rr.x; o.y += rr.y;
                }
                *(float2*)(cp + col) = o;
            }
        }
    }
}

// ---------------- attention: causal softmax, T=17, hd=64; h += o ----------------
__global__ void attn_kernel()
{
    __shared__ float qs[TT][65], ks[TT][65], vs[TT][65], sc[TT][20];
    const int bh = blockIdx.x;
    const int b = bh >> 4, hh = bh & 15;
    const size_t base3 = (size_t)b*TT*(3*CC) + hh*HD;
    const size_t baseh = (size_t)b*TT*CC + hh*HD;
    const int tid = threadIdx.x; // 128

    for (int idx = tid; idx < TT*HD; idx += 128) {
        int t = idx >> 6, d = idx & 63;
        size_t gg = base3 + (size_t)t*(3*CC) + d;
        qs[t][d] = g_qkv[gg];
        ks[t][d] = g_qkv[gg + CC];
        vs[t][d] = g_qkv[gg + 2*CC];
    }
    __syncthreads();

    for (int e = tid; e < TT*TT; e += 128) {
        int qi = e / TT, kj = e % TT;
        if (kj <= qi) {
            float a = 0.f;
            #pragma unroll
            for (int d = 0; d < HD; d++) a += qs[qi][d]*ks[kj][d];
            sc[qi][kj] = a * 0.125f;
        }
    }
    __syncthreads();

    if (tid < TT) {
        int t = tid;
        float m = -1e30f;
        for (int j = 0; j <= t; j++) m = fmaxf(m, sc[t][j]);
        float s = 0.f;
        for (int j = 0; j <= t; j++) { float e2 = __expf(sc[t][j]-m); sc[t][j] = e2; s += e2; }
        float inv = 1.f/s;
        for (int j = 0; j <= t; j++) sc[t][j] *= inv;
    }
    __syncthreads();

    for (int e = tid; e < TT*HD; e += 128) {
        int t = e >> 6, d = e & 63;
        float a = 0.f;
        for (int j = 0; j <= t; j++) a += sc[t][j]*vs[j][d];
        g_h[baseh + (size_t)t*CC + d] += a;
    }
}

// ---------------- fold out_w into conv decode ----------------
__global__ void w2_kernel(const float* __restrict__ out_w, const float* __restrict__ cw)
{
    __shared__ float col[CC];
    const int e = blockIdx.x;
    const int tid = threadIdx.x; // 256
    for (int c = tid; c < CC; c += 256) col[c] = out_w[(size_t)c*CC + e];
    __syncthreads();
    if (tid < PATCH_E) {
        float acc = 0.f;
        for (int c = 0; c < CC; c++) acc += col[c]*cw[(size_t)c*PATCH_E + tid];
        g_w2[(size_t)e*PATCH_E + tid] = acc;
    }
}

__global__ void b2_kernel(const float* __restrict__ out_b, const float* __restrict__ cw)
{
    const int n = threadIdx.x;
    if (n < PATCH_E) {
        float acc = 0.f;
        for (int c = 0; c < CC; c++) acc += out_b[c]*cw[(size_t)c*PATCH_E + n];
        g_b2[n] = acc;
    }
}

// ---------------- decode ----------------
__global__ void decode_kernel(float* __restrict__ out)
{
    __shared__ float sh[TOKB][CC];
    const int tok0 = blockIdx.x * TOKB;
    const int tid = threadIdx.x; // 256
    const float4* src = (const float4*)(g_h + (size_t)tok0*CC);
    for (int idx = tid; idx < TOKB*CC/4; idx += 256)
        ((float4*)sh)[idx] = src[idx];
    __syncthreads();

    const int n = tid;
    if (n < PATCH_E) {
        float acc[TOKB];
        #pragma unroll
        for (int t = 0; t < TOKB; t++) acc[t] = 0.f;
        for (int e = 0; e < CC; e++) {
            float wv = g_w2[(size_t)e*PATCH_E + n];
            #pragma unroll
            for (int t = 0; t < TOKB; t++) acc[t] += sh[t][e]*wv;
        }
        float bb = g_b2[n];
        int d = n / 49, hr = (n % 49) / 7, w = n % 7;
        #pragma unroll
        for (int t = 0; t < TOKB; t++) {
            int tok = tok0 + t;
            int b = tok / TT, s = tok % TT;
            out[((size_t)(b*3 + d)*7 + hr)*119 + s*7 + w] = acc[t] + bb;
        }
    }
}

// ---------------- launch ----------------
extern "C" void kernel_launch(void* const* d_in, const int* in_sizes, int n_in,
                              void* d_out, int out_size)
{
    const float* x      = (const float*)d_in[0];
    const float* conv_w = (const float*)d_in[1];
    const float* ln1_w  = (const float*)d_in[2];
    const float* ln1_b  = (const float*)d_in[3];
    const float* wq     = (const float*)d_in[4];
    const float* wk     = (const float*)d_in[5];
    const float* wv     = (const float*)d_in[6];
    const float* ln2_w  = (const float*)d_in[7];
    const float* ln2_b  = (const float*)d_in[8];
    const float* mlp_w  = (const float*)d_in[9];
    const float* mlp_b  = (const float*)d_in[10];
    const float* out_w  = (const float*)d_in[11];
    const float* out_b  = (const float*)d_in[12];
    float* out = (float*)d_out;

    void *ph, *pxn, *pqkv, *pwqkv, *pwmlp;
    cudaGetSymbolAddress(&ph,    g_h);
    cudaGetSymbolAddress(&pxn,   g_xn16);
    cudaGetSymbolAddress(&pqkv,  g_qkv);
    cudaGetSymbolAddress(&pwqkv, g_wqkv16);
    cudaGetSymbolAddress(&pwmlp, g_wmlp16);
    float*  h     = (float*)ph;
    __half* xn    = (__half*)pxn;
    float*  qkv   = (float*)pqkv;
    __half* wqkv16 = (__half*)pwqkv;
    __half* wmlp16 = (__half*)pwmlp;

    // pack weights to fp16 (runs inside the graph; ~40us)
    {
        size_t nq = (size_t)NL*3*CC*CC/4;
        pack_qkv_kernel<<<(unsigned)((nq + 255)/256), 256>>>(wq, wk, wv);
        size_t nm = (size_t)NL*CC*CC/4;
        pack_mlp_kernel<<<(unsigned)((nm + 255)/256), 256>>>(mlp_w);
    }

    embed_kernel<<<MM/TOKB, 256>>>(x, conv_w);

    dim3 gq(3*CC/128, MM/128);  // (24, 68)
    dim3 gm(CC/128,   MM/128);  // (8, 68)
    for (int l = 0; l < NL; l++) {
        const size_t vo = (size_t)l*CC;
        ln_kernel<<<MM, 256>>>(h, xn, ln1_w + vo, ln1_b + vo);
        gemm_fp16<<<gq, 256>>>(xn, wqkv16 + (size_t)l*3*CC*CC, 3*CC, nullptr, nullptr, qkv);
        attn_kernel<<<BB*NH, 128>>>();
        ln_kernel<<<MM, 256>>>(h, xn, ln2_w + vo, ln2_b + vo);
        gemm_fp16<<<gm, 256>>>(xn, wmlp16 + (size_t)l*CC*CC, CC, mlp_b + vo, h, h);
    }

    w2_kernel<<<CC, 256>>>(out_w, conv_w);
    b2_kernel<<<1, 160>>>(out_b, conv_w);
    decode_kernel<<<MM/TOKB, 256>>>(out);
}